// round 3
// baseline (speedup 1.0000x reference)
#include <cuda_runtime.h>
#include <math.h>

#define WSZ    32
#define NH     31
#define NPATCH (NH * NH)   // 961
#define NB     16
#define NC     3
#define IH     512
#define IW     512

// ---------------- device globals (no allocations allowed) ----------------
__device__ float gDT[16 * 32];          // gDT[j*32+i] = D[i][j], j < 16 (symmetry-folded half)
__device__ float gW[64];                // diagonal weight table W[s], s = i+k in [0,62]
__device__ float gGrade[NB * NPATCH];
__device__ int   gSel[NB * 4];          // per batch: [minmin, maxmax, minmin1, maxmax1]

// ---------------- init: DCT matrix + grade-weight table ----------------
// Replicates numpy's float64 arithmetic for the filter boundaries exactly.
__global__ void init_kernel() {
    int tid = threadIdx.x;               // 512 threads: i = row 0..31, j = col 0..15
    int i = tid >> 4, j = tid & 15;
    double scale = (i == 0) ? sqrt(1.0 / 32.0) : sqrt(2.0 / 32.0);
    double v = scale * cos((((double)j + 0.5) * 3.141592653589793) * (double)i / 32.0);
    gDT[j * 32 + i] = (float)v;

    if (tid == 0) {
        float Wl[64];
        #pragma unroll
        for (int s = 0; s < 64; s++) Wl[s] = 0.0f;
        double q = (double)WSZ * 2.0 / 6.0;           // 64/6 in IEEE double, like numpy
        for (int g = 0; g < 6; g++) {
            double st = q * (double)g;
            double en = q * (double)(g + 1);
            float ft = 0.0f;                          // ft_num as float32 sum (exact ints)
            for (int s = 0; s <= 62; s++) {
                bool in = !((double)s > en || (double)s < st);
                if (in) ft += (float)((s <= 31) ? (s + 1) : (63 - s));
            }
            float coef = ((float)(1 << g)) / ft;      // float32 division, like numpy
            for (int s = 0; s <= 62; s++) {
                bool in = !((double)s > en || (double)s < st);
                if (in) Wl[s] += coef;
            }
        }
        for (int s = 0; s < 64; s++) gW[s] = Wl[s];
    }
}

// ---------------- grade: per-patch 2D DCT + weighted log reduce ----------------
// Block = one (b, patch). 256 threads. Even/odd DCT symmetry halves FMAs.
// Inner loops: 1 conflict-free scalar LDS + 1 float4 broadcast LDS per 4 FMAs.
__global__ __launch_bounds__(256) void grade_kernel(const float* __restrict__ x) {
    // Xs is reused as the stage-1 output O1 (same [c][r][33] padded layout).
    __shared__ __align__(16) float Xs[NC * 32 * 33];
    __shared__ __align__(16) float U1[NC * 16 * 32];  // U1[c][j'][r] = x[r][j'] + x[r][31-j']
    __shared__ __align__(16) float V1[NC * 16 * 32];
    __shared__ __align__(16) float U2[NC * 16 * 32];  // U2[c][r'][k] = O1[r'][k] + O1[31-r'][k]
    __shared__ __align__(16) float V2[NC * 16 * 32];
    __shared__ float DT[16 * 32];
    __shared__ float Wt[64];
    __shared__ float red[8];

    const int bl  = blockIdx.x;
    const int b   = bl / NPATCH;
    const int l   = bl - b * NPATCH;
    const int hr  = l / NH;
    const int wc  = l - hr * NH;
    const int tid = threadIdx.x;

    // constants to smem
    for (int i = tid; i < 512; i += 256) DT[i] = gDT[i];
    if (tid < 64) Wt[tid] = gW[tid];

    // load 3x32x32 patch (rows are 128B contiguous & coalesced)
    const float* xb = x + ((size_t)b * NC) * IH * IW;
    for (int idx = tid; idx < NC * 32 * 32; idx += 256) {
        int j = idx & 31;
        int r = (idx >> 5) & 31;
        int c = idx >> 10;
        Xs[(c * 32 + r) * 33 + j] =
            xb[((size_t)c * IH + (hr * 16 + r)) * IW + (wc * 16 + j)];
    }
    __syncthreads();

    // fold columns: U1/V1 (transposed so stage-1 reads rows as float4)
    for (int idx = tid; idx < NC * 16 * 32; idx += 256) {
        int r  = idx & 31;
        int jp = (idx >> 5) & 15;
        int c  = idx >> 9;
        float a  = Xs[(c * 32 + r) * 33 + jp];
        float bb = Xs[(c * 32 + r) * 33 + (31 - jp)];
        U1[(c * 16 + jp) * 32 + r] = a + bb;
        V1[(c * 16 + jp) * 32 + r] = a - bb;
    }
    __syncthreads();

    // ---- stage 1: O1[r][k] = sum_j P[r][j] * D[k][j]  (row DCT) ----
    // thread: k = lane (0..31), warp handles rows 4*rq .. 4*rq+3
    {
        const int k  = tid & 31;
        const int rq = tid >> 5;
        const float* Wb = (k & 1) ? V1 : U1;   // even k uses U (sum), odd uses V (diff)
        for (int c = 0; c < NC; c++) {
            float a0 = 0.f, a1 = 0.f, a2 = 0.f, a3 = 0.f;
            #pragma unroll
            for (int jp = 0; jp < 16; jp++) {
                float d  = DT[jp * 32 + k];                               // conflict-free
                float4 w = *(const float4*)(Wb + ((c * 16 + jp) << 5) + (rq << 2)); // broadcast
                a0 = fmaf(w.x, d, a0);
                a1 = fmaf(w.y, d, a1);
                a2 = fmaf(w.z, d, a2);
                a3 = fmaf(w.w, d, a3);
            }
            // O1 lives in Xs (input tile is dead now); row writes are contiguous in k
            Xs[(c * 32 + rq * 4 + 0) * 33 + k] = a0;
            Xs[(c * 32 + rq * 4 + 1) * 33 + k] = a1;
            Xs[(c * 32 + rq * 4 + 2) * 33 + k] = a2;
            Xs[(c * 32 + rq * 4 + 3) * 33 + k] = a3;
        }
    }
    __syncthreads();

    // fold rows: U2/V2
    for (int idx = tid; idx < NC * 16 * 32; idx += 256) {
        int kk = idx & 31;
        int rp = (idx >> 5) & 15;
        int c  = idx >> 9;
        float a  = Xs[(c * 32 + rp) * 33 + kk];
        float bb = Xs[(c * 32 + (31 - rp)) * 33 + kk];
        U2[(c * 16 + rp) * 32 + kk] = a + bb;
        V2[(c * 16 + rp) * 32 + kk] = a - bb;
    }
    __syncthreads();

    // ---- stage 2 + grade: dct[i][k] = sum_r D[i][r]*O1[r][k]; acc W[i+k]*log(|dct|+1) ----
    float g = 0.0f;
    {
        const int i2 = tid & 31;
        const int kq = tid >> 5;
        const float* Wb = (i2 & 1) ? V2 : U2;
        for (int c = 0; c < NC; c++) {
            float a0 = 0.f, a1 = 0.f, a2 = 0.f, a3 = 0.f;
            #pragma unroll
            for (int rp = 0; rp < 16; rp++) {
                float d  = DT[rp * 32 + i2];                               // conflict-free
                float4 w = *(const float4*)(Wb + ((c * 16 + rp) << 5) + (kq << 2)); // broadcast
                a0 = fmaf(w.x, d, a0);
                a1 = fmaf(w.y, d, a1);
                a2 = fmaf(w.z, d, a2);
                a3 = fmaf(w.w, d, a3);
            }
            int k0 = kq * 4;
            g += __logf(fabsf(a0) + 1.0f) * Wt[i2 + k0 + 0];
            g += __logf(fabsf(a1) + 1.0f) * Wt[i2 + k0 + 1];
            g += __logf(fabsf(a2) + 1.0f) * Wt[i2 + k0 + 2];
            g += __logf(fabsf(a3) + 1.0f) * Wt[i2 + k0 + 3];
        }
    }
    // block reduce
    #pragma unroll
    for (int off = 16; off > 0; off >>= 1) g += __shfl_down_sync(0xFFFFFFFFu, g, off);
    if ((tid & 31) == 0) red[tid >> 5] = g;
    __syncthreads();
    if (tid < 8) {
        float v = red[tid];
        #pragma unroll
        for (int off = 4; off > 0; off >>= 1) v += __shfl_down_sync(0xFFu, v, off);
        if (tid == 0) gGrade[bl] = v;
    }
}

// ---------------- selection: stable-argsort-compatible top2/bottom2 ----------------
__global__ void select_kernel() {
    __shared__ unsigned long long smin[256][2];
    __shared__ unsigned long long smax[256][2];
    const int b   = blockIdx.x;
    const int tid = threadIdx.x;
    const float* gr = &gGrade[b * NPATCH];

    unsigned long long mn1 = ~0ull, mn2 = ~0ull, mx1 = 0ull, mx2 = 0ull;
    for (int l = tid; l < NPATCH; l += 256) {
        unsigned int ub = __float_as_uint(gr[l]);
        ub = (ub & 0x80000000u) ? ~ub : (ub | 0x80000000u);   // order-preserving map
        unsigned long long key = ((unsigned long long)ub << 32) | (unsigned)l;
        if (key < mn1) { mn2 = mn1; mn1 = key; } else if (key < mn2) { mn2 = key; }
        if (key > mx1) { mx2 = mx1; mx1 = key; } else if (key > mx2) { mx2 = key; }
    }
    smin[tid][0] = mn1; smin[tid][1] = mn2;
    smax[tid][0] = mx1; smax[tid][1] = mx2;
    __syncthreads();
    #pragma unroll
    for (int s = 128; s > 0; s >>= 1) {
        if (tid < s) {
            unsigned long long a1 = smin[tid][0], a2 = smin[tid][1];
            unsigned long long b1 = smin[tid + s][0], b2 = smin[tid + s][1];
            smin[tid][0] = min(a1, b1);
            smin[tid][1] = min(max(a1, b1), min(a2, b2));
            a1 = smax[tid][0]; a2 = smax[tid][1];
            b1 = smax[tid + s][0]; b2 = smax[tid + s][1];
            smax[tid][0] = max(a1, b1);
            smax[tid][1] = max(min(a1, b1), max(a2, b2));
        }
        __syncthreads();
    }
    if (tid == 0) {
        gSel[b * 4 + 0] = (int)(smin[0][0] & 0xFFFFFFFFull);  // minmin  = idx[0]
        gSel[b * 4 + 1] = (int)(smax[0][0] & 0xFFFFFFFFull);  // maxmax  = idx[-1]
        gSel[b * 4 + 2] = (int)(smin[0][1] & 0xFFFFFFFFull);  // minmin1 = idx[1]
        gSel[b * 4 + 3] = (int)(smax[0][1] & 0xFFFFFFFFull);  // maxmax1 = idx[-2]
    }
}

// ---------------- gather: level_y == patch (orthogonal DCT round-trip) ----------------
// out layout: [x_minmin | x_maxmax | x_minmin1 | x_maxmax1], each (16,3,32,32)
__global__ void gather_kernel(const float* __restrict__ x, float* __restrict__ out) {
    const int id  = blockIdx.x;            // sel*48 + b*3 + c
    const int sel = id / 48;
    const int bc  = id - sel * 48;
    const int b   = bc / 3;
    const int c   = bc - b * 3;
    const int l   = gSel[b * 4 + sel];
    const int hr  = l / NH;
    const int wc  = l - hr * NH;

    const float4* src = (const float4*)(x + (((size_t)(b * NC + c)) * IH + hr * 16) * IW + wc * 16);
    float4* dst = (float4*)(out + (size_t)id * 1024);
    const int t  = threadIdx.x;            // 256 threads, one float4 each
    const int r  = t >> 3;
    const int jq = t & 7;
    dst[r * 8 + jq] = src[r * (IW / 4) + jq];
}

// ---------------- launch ----------------
extern "C" void kernel_launch(void* const* d_in, const int* in_sizes, int n_in,
                              void* d_out, int out_size) {
    const float* x = (const float*)d_in[0];
    float* out = (float*)d_out;
    init_kernel<<<1, 512>>>();
    grade_kernel<<<NB * NPATCH, 256>>>(x);
    select_kernel<<<NB, 256>>>();
    gather_kernel<<<4 * NB * NC, 256>>>(x, out);
}

// round 5
// speedup vs baseline: 1.0478x; 1.0478x over previous
#include <cuda_runtime.h>
#include <math.h>

#define WSZ    32
#define NH     31
#define NPATCH (NH * NH)   // 961
#define NB     16
#define NC     3
#define IH     512
#define IW     512

// ---------------- device globals (no allocations allowed) ----------------
__device__ float gDT[16 * 32];            // gDT[j*32+i] = D[i][j], j < 16 (symmetry half)
__device__ float gW[64];                  // diagonal weight table W[s], s = i+k in [0,62]
__device__ float gGradeC[NB * NPATCH * 4]; // per-channel partial grades, stride 4 (c=0..2)
__device__ int   gSel[NB * 4];            // per batch: [minmin, maxmax, minmin1, maxmax1]

// ---------------- init: DCT matrix + grade-weight table ----------------
__global__ void init_kernel() {
    int tid = threadIdx.x;               // 512 threads: i = row 0..31, j = col 0..15
    int i = tid >> 4, j = tid & 15;
    double scale = (i == 0) ? sqrt(1.0 / 32.0) : sqrt(2.0 / 32.0);
    double v = scale * cos((((double)j + 0.5) * 3.141592653589793) * (double)i / 32.0);
    gDT[j * 32 + i] = (float)v;

    if (tid == 0) {
        float Wl[64];
        #pragma unroll
        for (int s = 0; s < 64; s++) Wl[s] = 0.0f;
        double q = (double)WSZ * 2.0 / 6.0;           // 64/6 in IEEE double, like numpy
        for (int g = 0; g < 6; g++) {
            double st = q * (double)g;
            double en = q * (double)(g + 1);
            float ft = 0.0f;
            for (int s = 0; s <= 62; s++) {
                bool in = !((double)s > en || (double)s < st);
                if (in) ft += (float)((s <= 31) ? (s + 1) : (63 - s));
            }
            float coef = ((float)(1 << g)) / ft;
            for (int s = 0; s <= 62; s++) {
                bool in = !((double)s > en || (double)s < st);
                if (in) Wl[s] += coef;
            }
        }
        for (int s = 0; s < 64; s++) gW[s] = Wl[s];
    }
}

// ---------------- grade: one (b, patch, channel) per block ----------------
// 256 threads. D kept in 16 registers (same for both stages, lane-indexed).
// fold-2 fused into stage-1 epilogue via rho-permuted row order.
__global__ __launch_bounds__(256) void grade_kernel(const float* __restrict__ x) {
    __shared__ __align__(16) float Xs[32 * 33];
    __shared__ __align__(16) float U1[16 * 32];
    __shared__ __align__(16) float V1[16 * 32];
    __shared__ __align__(16) float U2[16 * 32];
    __shared__ __align__(16) float V2[16 * 32];
    __shared__ float Wt[64];
    __shared__ float red[8];

    const int idx0 = blockIdx.x;         // (b*961 + l)*3 + c  (same-patch channels adjacent)
    const int c    = idx0 % 3;
    const int pl   = idx0 / 3;
    const int b    = pl / NPATCH;
    const int l    = pl - b * NPATCH;
    const int hr   = l / NH;
    const int wc   = l - hr * NH;
    const int tid  = threadIdx.x;
    const int lane = tid & 31;
    const int wq   = tid >> 5;           // warp id 0..7

    // D half-matrix column for this lane: D[lane][jp] == gDT[jp*32+lane]
    float dreg[16];
    #pragma unroll
    for (int jp = 0; jp < 16; jp++) dreg[jp] = __ldg(&gDT[jp * 32 + lane]);
    if (tid < 64) Wt[tid] = gW[tid];

    // load this channel's 32x32 patch: 1 float4 per thread, coalesced
    const float* xc = x + (((size_t)(b * NC + c)) * IH + hr * 16) * IW + wc * 16;
    {
        const int r = tid >> 3, q = tid & 7;
        float4 g4 = *(const float4*)(xc + (size_t)r * IW + q * 4);
        float* row = &Xs[r * 33 + 4 * q];
        row[0] = g4.x; row[1] = g4.y; row[2] = g4.z; row[3] = g4.w;
    }
    __syncthreads();

    // fold-1 (columns j): write U1/V1 with rows in rho-order so stage-1's float4
    // quad 4*wq covers rows {2wq, 2wq+1, 30-2wq, 31-2wq}
    #pragma unroll
    for (int s = 0; s < 2; s++) {
        int id2 = tid + s * 256;
        int r  = id2 & 31;
        int jp = id2 >> 5;
        float a  = Xs[r * 33 + jp];
        float bb = Xs[r * 33 + 31 - jp];
        int rho = (r < 16) ? (2 * r - (r & 1)) : ((r & 1) ? (65 - 2 * r) : (62 - 2 * r));
        U1[jp * 32 + rho] = a + bb;
        V1[jp * 32 + rho] = a - bb;
    }
    __syncthreads();

    // stage 1: O1[r][k] = sum_j x[r][j] D[k][j]; lane = k, warp wq owns 4 symmetric rows.
    // Fused fold-2: write U2/V2 directly from register pairs.
    {
        const float* Wb = (lane & 1) ? V1 : U1;    // even k -> U (sum), odd k -> V (diff)
        float a0 = 0.f, a1 = 0.f, a2 = 0.f, a3 = 0.f;
        #pragma unroll
        for (int jp = 0; jp < 16; jp++) {
            float4 w = *(const float4*)(Wb + jp * 32 + 4 * wq);   // uniform addr per warp
            float d = dreg[jp];
            a0 = fmaf(w.x, d, a0);   // row 2wq
            a1 = fmaf(w.y, d, a1);   // row 2wq+1
            a2 = fmaf(w.z, d, a2);   // row 30-2wq
            a3 = fmaf(w.w, d, a3);   // row 31-2wq
        }
        U2[(2 * wq) * 32 + lane]     = a0 + a3;   // O1[2wq]   + O1[31-2wq]
        U2[(2 * wq + 1) * 32 + lane] = a1 + a2;   // O1[2wq+1] + O1[30-2wq]
        V2[(2 * wq) * 32 + lane]     = a0 - a3;
        V2[(2 * wq + 1) * 32 + lane] = a1 - a2;
    }
    __syncthreads();

    // stage 2 + grade: dct[i][k] = sum_rp D[i][rp] * (U2|V2)[rp][k]; lane = i, warp wq -> k quad
    float g = 0.0f;
    {
        const float* Wb = (lane & 1) ? V2 : U2;
        float a0 = 0.f, a1 = 0.f, a2 = 0.f, a3 = 0.f;
        #pragma unroll
        for (int rp = 0; rp < 16; rp++) {
            float4 w = *(const float4*)(Wb + rp * 32 + 4 * wq);
            float d = dreg[rp];
            a0 = fmaf(w.x, d, a0);
            a1 = fmaf(w.y, d, a1);
            a2 = fmaf(w.z, d, a2);
            a3 = fmaf(w.w, d, a3);
        }
        const int k0 = 4 * wq;
        g  = __logf(fabsf(a0) + 1.0f) * Wt[lane + k0 + 0];
        g += __logf(fabsf(a1) + 1.0f) * Wt[lane + k0 + 1];
        g += __logf(fabsf(a2) + 1.0f) * Wt[lane + k0 + 2];
        g += __logf(fabsf(a3) + 1.0f) * Wt[lane + k0 + 3];
    }
    // block reduce
    #pragma unroll
    for (int off = 16; off > 0; off >>= 1) g += __shfl_down_sync(0xFFFFFFFFu, g, off);
    if (lane == 0) red[wq] = g;
    __syncthreads();
    if (tid < 8) {
        float v = red[tid];
        #pragma unroll
        for (int off = 4; off > 0; off >>= 1) v += __shfl_down_sync(0xFFu, v, off);
        if (tid == 0) gGradeC[pl * 4 + c] = v;
    }
}

// ---------------- selection: stable-argsort-compatible top2/bottom2 ----------------
__global__ void select_kernel() {
    __shared__ unsigned long long smin[256][2];
    __shared__ unsigned long long smax[256][2];
    const int b   = blockIdx.x;
    const int tid = threadIdx.x;
    const float* gr = &gGradeC[b * NPATCH * 4];

    unsigned long long mn1 = ~0ull, mn2 = ~0ull, mx1 = 0ull, mx2 = 0ull;
    for (int l = tid; l < NPATCH; l += 256) {
        float val = gr[l * 4 + 0] + gr[l * 4 + 1] + gr[l * 4 + 2];
        unsigned int ub = __float_as_uint(val);
        ub = (ub & 0x80000000u) ? ~ub : (ub | 0x80000000u);   // order-preserving map
        unsigned long long key = ((unsigned long long)ub << 32) | (unsigned)l;
        if (key < mn1) { mn2 = mn1; mn1 = key; } else if (key < mn2) { mn2 = key; }
        if (key > mx1) { mx2 = mx1; mx1 = key; } else if (key > mx2) { mx2 = key; }
    }
    smin[tid][0] = mn1; smin[tid][1] = mn2;
    smax[tid][0] = mx1; smax[tid][1] = mx2;
    __syncthreads();
    for (int s = 128; s > 0; s >>= 1) {
        if (tid < s) {
            unsigned long long a1 = smin[tid][0], a2 = smin[tid][1];
            unsigned long long b1 = smin[tid + s][0], b2 = smin[tid + s][1];
            smin[tid][0] = min(a1, b1);
            smin[tid][1] = min(max(a1, b1), min(a2, b2));
            a1 = smax[tid][0]; a2 = smax[tid][1];
            b1 = smax[tid + s][0]; b2 = smax[tid + s][1];
            smax[tid][0] = max(a1, b1);
            smax[tid][1] = max(min(a1, b1), max(a2, b2));
        }
        __syncthreads();
    }
    if (tid == 0) {
        gSel[b * 4 + 0] = (int)(smin[0][0] & 0xFFFFFFFFull);  // minmin  = idx[0]
        gSel[b * 4 + 1] = (int)(smax[0][0] & 0xFFFFFFFFull);  // maxmax  = idx[-1]
        gSel[b * 4 + 2] = (int)(smin[0][1] & 0xFFFFFFFFull);  // minmin1 = idx[1]
        gSel[b * 4 + 3] = (int)(smax[0][1] & 0xFFFFFFFFull);  // maxmax1 = idx[-2]
    }
}

// ---------------- gather: level_y == patch (orthogonal DCT round-trip) ----------------
// out layout: [x_minmin | x_maxmax | x_minmin1 | x_maxmax1], each (16,3,32,32)
__global__ void gather_kernel(const float* __restrict__ x, float* __restrict__ out) {
    const int id  = blockIdx.x;            // sel*48 + b*3 + c
    const int sel = id / 48;
    const int bc  = id - sel * 48;
    const int b   = bc / 3;
    const int c   = bc - b * 3;
    const int l   = gSel[b * 4 + sel];
    const int hr  = l / NH;
    const int wc  = l - hr * NH;

    const float4* src = (const float4*)(x + (((size_t)(b * NC + c)) * IH + hr * 16) * IW + wc * 16);
    float4* dst = (float4*)(out + (size_t)id * 1024);
    const int t  = threadIdx.x;            // 256 threads, one float4 each
    const int r  = t >> 3;
    const int jq = t & 7;
    dst[r * 8 + jq] = src[r * (IW / 4) + jq];
}

// ---------------- launch ----------------
extern "C" void kernel_launch(void* const* d_in, const int* in_sizes, int n_in,
                              void* d_out, int out_size) {
    const float* x = (const float*)d_in[0];
    float* out = (float*)d_out;
    init_kernel<<<1, 512>>>();
    grade_kernel<<<NB * NPATCH * NC, 256>>>(x);
    select_kernel<<<NB, 256>>>();
    gather_kernel<<<4 * NB * NC, 256>>>(x, out);
}

// round 7
// speedup vs baseline: 1.0958x; 1.0458x over previous
#include <cuda_runtime.h>
#include <math.h>

#define WSZ    32
#define NH     31
#define NPATCH (NH * NH)   // 961
#define NB     16
#define NC     3
#define IH     512
#define IW     512

#define STRIDE_S 513                    // strip row stride in floats (odd -> conflict-free)
#define SMEM_FLOATS (32 * STRIDE_S + 4 * 512 + 64 + 8 * NH)
#define SMEM_BYTES  (SMEM_FLOATS * 4)

// ---------------- device globals (no allocations allowed) ----------------
__device__ float gDT[16 * 32];            // gDT[j*32+i] = D[i][j], j < 16 (symmetry half)
__device__ float gW[64];                  // diagonal weight table W[s], s = i+k in [0,62]
__device__ float gGradeC[NB * NPATCH * 4]; // per-channel partial grades, stride 4 (c=0..2)
__device__ int   gSel[NB * 4];            // per batch: [minmin, maxmax, minmin1, maxmax1]

// ---------------- init: DCT matrix + grade-weight table ----------------
__global__ void init_kernel() {
    int tid = threadIdx.x;               // 512 threads: i = row 0..31, j = col 0..15
    int i = tid >> 4, j = tid & 15;
    double scale = (i == 0) ? sqrt(1.0 / 32.0) : sqrt(2.0 / 32.0);
    double v = scale * cos((((double)j + 0.5) * 3.141592653589793) * (double)i / 32.0);
    gDT[j * 32 + i] = (float)v;

    if (tid == 0) {
        float Wl[64];
        #pragma unroll
        for (int s = 0; s < 64; s++) Wl[s] = 0.0f;
        double q = (double)WSZ * 2.0 / 6.0;           // 64/6 in IEEE double, like numpy
        for (int g = 0; g < 6; g++) {
            double st = q * (double)g;
            double en = q * (double)(g + 1);
            float ft = 0.0f;
            for (int s = 0; s <= 62; s++) {
                bool in = !((double)s > en || (double)s < st);
                if (in) ft += (float)((s <= 31) ? (s + 1) : (63 - s));
            }
            float coef = ((float)(1 << g)) / ft;
            for (int s = 0; s <= 62; s++) {
                bool in = !((double)s > en || (double)s < st);
                if (in) Wl[s] += coef;
            }
        }
        for (int s = 0; s < 64; s++) gW[s] = Wl[s];
    }
}

// ---------------- grade: one (b, hr, c) row-strip per block, 31 patches ----------------
__global__ __launch_bounds__(256) void grade_kernel(const float* __restrict__ x) {
    extern __shared__ __align__(16) float sm[];
    float* strip = sm;                        // [32][513]
    float* U1    = sm + 32 * STRIDE_S;        // [16][32]
    float* V1    = U1 + 512;
    float* U2    = V1 + 512;
    float* V2    = U2 + 512;
    float* Wt    = V2 + 512;                  // [64]
    float* gpart = Wt + 64;                   // [8][31]

    const int idx0 = blockIdx.x;              // ((b*31 + hr)*3 + c)
    const int c    = idx0 % 3;
    const int bh   = idx0 / 3;
    const int hr   = bh % NH;
    const int b    = bh / NH;
    const int tid  = threadIdx.x;
    const int lane = tid & 31;
    const int wq   = tid >> 5;                // warp id 0..7

    // D half-matrix column for this lane (shared by both stages)
    float dreg[16];
    #pragma unroll
    for (int jp = 0; jp < 16; jp++) dreg[jp] = __ldg(&gDT[jp * 32 + lane]);
    if (tid < 64) Wt[tid] = gW[tid];

    // load strip: rows 16hr..16hr+31, full 512 width. float4 gmem, scalar smem stores.
    const float* xs = x + (((size_t)(b * NC + c)) * IH + hr * 16) * IW;
    #pragma unroll
    for (int i = 0; i < 16; i++) {
        int idx = tid + i * 256;              // 0..4095 float4s
        int r   = idx >> 7;                   // 128 float4 per row
        int q   = idx & 127;
        float4 g4 = *(const float4*)(xs + (size_t)r * IW + q * 4);
        float* row = strip + r * STRIDE_S + q * 4;
        row[0] = g4.x; row[1] = g4.y; row[2] = g4.z; row[3] = g4.w;
    }
    __syncthreads();

    // rho row-permutation: stage-1 quad 4*w covers rows {2w, 2w+1, 30-2w, 31-2w}
    const int rho = (lane < 16) ? (2 * lane - (lane & 1))
                                : ((lane & 1) ? (65 - 2 * lane) : (62 - 2 * lane));

    for (int p = 0; p < NH; p++) {
        const int off = p * 16;

        // fold-1 (columns): r = lane, jp = wq (+8). conflict-free reads & writes.
        #pragma unroll
        for (int s = 0; s < 2; s++) {
            int jp = wq + 8 * s;
            const float* row = strip + lane * STRIDE_S + off;
            float a  = row[jp];
            float bb = row[31 - jp];
            U1[jp * 32 + rho] = a + bb;
            V1[jp * 32 + rho] = a - bb;
        }
        __syncthreads();

        // stage 1 + fused fold-2: lane = k, warp wq -> 4 symmetric rows
        {
            const float* Wb = (lane & 1) ? V1 : U1;
            float a0 = 0.f, a1 = 0.f, a2 = 0.f, a3 = 0.f;
            #pragma unroll
            for (int jp = 0; jp < 16; jp++) {
                float4 w = *(const float4*)(Wb + jp * 32 + 4 * wq);  // uniform per warp
                float d = dreg[jp];
                a0 = fmaf(w.x, d, a0);
                a1 = fmaf(w.y, d, a1);
                a2 = fmaf(w.z, d, a2);
                a3 = fmaf(w.w, d, a3);
            }
            U2[(2 * wq) * 32 + lane]     = a0 + a3;
            U2[(2 * wq + 1) * 32 + lane] = a1 + a2;
            V2[(2 * wq) * 32 + lane]     = a0 - a3;
            V2[(2 * wq + 1) * 32 + lane] = a1 - a2;
        }
        __syncthreads();

        // stage 2 + grade partial: lane = i, warp wq -> k quad
        {
            const float* Wb = (lane & 1) ? V2 : U2;
            float a0 = 0.f, a1 = 0.f, a2 = 0.f, a3 = 0.f;
            #pragma unroll
            for (int rp = 0; rp < 16; rp++) {
                float4 w = *(const float4*)(Wb + rp * 32 + 4 * wq);
                float d = dreg[rp];
                a0 = fmaf(w.x, d, a0);
                a1 = fmaf(w.y, d, a1);
                a2 = fmaf(w.z, d, a2);
                a3 = fmaf(w.w, d, a3);
            }
            const int k0 = 4 * wq;
            float g;
            g  = __logf(fabsf(a0) + 1.0f) * Wt[lane + k0 + 0];
            g += __logf(fabsf(a1) + 1.0f) * Wt[lane + k0 + 1];
            g += __logf(fabsf(a2) + 1.0f) * Wt[lane + k0 + 2];
            g += __logf(fabsf(a3) + 1.0f) * Wt[lane + k0 + 3];
            #pragma unroll
            for (int o = 16; o > 0; o >>= 1) g += __shfl_down_sync(0xFFFFFFFFu, g, o);
            if (lane == 0) gpart[wq * NH + p] = g;
        }
        __syncthreads();   // protects U1/V1,U2/V2 reuse next patch; final sync covers gpart
    }

    // deferred 8-warp sums -> gGradeC
    if (tid < NH) {
        float s = 0.f;
        #pragma unroll
        for (int w = 0; w < 8; w++) s += gpart[w * NH + tid];
        int pl = b * NPATCH + hr * NH + tid;
        gGradeC[pl * 4 + c] = s;
    }
}

// ---------------- selection: stable-argsort-compatible top2/bottom2 ----------------
__global__ void select_kernel() {
    __shared__ unsigned long long smin[256][2];
    __shared__ unsigned long long smax[256][2];
    const int b   = blockIdx.x;
    const int tid = threadIdx.x;
    const float* gr = &gGradeC[b * NPATCH * 4];

    unsigned long long mn1 = ~0ull, mn2 = ~0ull, mx1 = 0ull, mx2 = 0ull;
    for (int l = tid; l < NPATCH; l += 256) {
        float val = gr[l * 4 + 0] + gr[l * 4 + 1] + gr[l * 4 + 2];
        unsigned int ub = __float_as_uint(val);
        ub = (ub & 0x80000000u) ? ~ub : (ub | 0x80000000u);   // order-preserving map
        unsigned long long key = ((unsigned long long)ub << 32) | (unsigned)l;
        if (key < mn1) { mn2 = mn1; mn1 = key; } else if (key < mn2) { mn2 = key; }
        if (key > mx1) { mx2 = mx1; mx1 = key; } else if (key > mx2) { mx2 = key; }
    }
    smin[tid][0] = mn1; smin[tid][1] = mn2;
    smax[tid][0] = mx1; smax[tid][1] = mx2;
    __syncthreads();
    for (int s = 128; s > 0; s >>= 1) {
        if (tid < s) {
            unsigned long long a1 = smin[tid][0], a2 = smin[tid][1];
            unsigned long long b1 = smin[tid + s][0], b2 = smin[tid + s][1];
            smin[tid][0] = min(a1, b1);
            smin[tid][1] = min(max(a1, b1), min(a2, b2));
            a1 = smax[tid][0]; a2 = smax[tid][1];
            b1 = smax[tid + s][0]; b2 = smax[tid + s][1];
            smax[tid][0] = max(a1, b1);
            smax[tid][1] = max(min(a1, b1), max(a2, b2));
        }
        __syncthreads();
    }
    if (tid == 0) {
        gSel[b * 4 + 0] = (int)(smin[0][0] & 0xFFFFFFFFull);  // minmin  = idx[0]
        gSel[b * 4 + 1] = (int)(smax[0][0] & 0xFFFFFFFFull);  // maxmax  = idx[-1]
        gSel[b * 4 + 2] = (int)(smin[0][1] & 0xFFFFFFFFull);  // minmin1 = idx[1]
        gSel[b * 4 + 3] = (int)(smax[0][1] & 0xFFFFFFFFull);  // maxmax1 = idx[-2]
    }
}

// ---------------- gather: level_y == patch (orthogonal DCT round-trip) ----------------
__global__ void gather_kernel(const float* __restrict__ x, float* __restrict__ out) {
    const int id  = blockIdx.x;            // sel*48 + b*3 + c
    const int sel = id / 48;
    const int bc  = id - sel * 48;
    const int b   = bc / 3;
    const int c   = bc - b * 3;
    const int l   = gSel[b * 4 + sel];
    const int hr  = l / NH;
    const int wc  = l - hr * NH;

    const float4* src = (const float4*)(x + (((size_t)(b * NC + c)) * IH + hr * 16) * IW + wc * 16);
    float4* dst = (float4*)(out + (size_t)id * 1024);
    const int t  = threadIdx.x;            // 256 threads, one float4 each
    const int r  = t >> 3;
    const int jq = t & 7;
    dst[r * 8 + jq] = src[r * (IW / 4) + jq];
}

// ---------------- launch ----------------
extern "C" void kernel_launch(void* const* d_in, const int* in_sizes, int n_in,
                              void* d_out, int out_size) {
    const float* x = (const float*)d_in[0];
    float* out = (float*)d_out;
    static int configured = 0;
    if (!configured) {
        cudaFuncSetAttribute(grade_kernel, cudaFuncAttributeMaxDynamicSharedMemorySize, SMEM_BYTES);
        configured = 1;
    }
    init_kernel<<<1, 512>>>();
    grade_kernel<<<NB * NH * NC, 256, SMEM_BYTES>>>(x);
    select_kernel<<<NB, 256>>>();
    gather_kernel<<<4 * NB * NC, 256>>>(x, out);
}

// round 8
// speedup vs baseline: 1.4224x; 1.2980x over previous
#include <cuda_runtime.h>
#include <math.h>

#define WSZ    32
#define NH     31
#define NPATCH (NH * NH)   // 961
#define NB     16
#define NC     3
#define IH     512
#define IW     512

#define STRIDE_S 273                    // strip row stride in floats (odd -> conflict-free)

// ---------------- device globals (no allocations allowed) ----------------
__device__ float gDT[16 * 32];            // gDT[j*32+i] = D[i][j], j < 16 (symmetry half)
__device__ float gW[64];                  // diagonal weight table W[s], s = i+k in [0,62]
__device__ float gGradeC[NB * NPATCH * 4]; // per-channel partial grades, stride 4 (c=0..2)
__device__ int   gSel[NB * 4];            // per batch: [minmin, maxmax, minmin1, maxmax1]

// ---------------- init: DCT matrix + grade-weight table (fully parallel) ----------------
__global__ void init_kernel() {
    __shared__ float sft[6];
    const int tid = threadIdx.x;         // 512 threads
    const int i = tid >> 4, j = tid & 15;
    double scale = (i == 0) ? sqrt(1.0 / 32.0) : sqrt(2.0 / 32.0);
    double v = scale * cos((((double)j + 0.5) * 3.141592653589793) * (double)i / 32.0);
    gDT[j * 32 + i] = (float)v;

    const double q = (double)WSZ * 2.0 / 6.0;         // 64/6 in IEEE double, like numpy
    if (tid < 6) {                                    // ft_num per band (float adds, exact ints)
        double st = q * (double)tid;
        double en = q * (double)(tid + 1);
        float ft = 0.0f;
        for (int s = 0; s <= 62; s++) {
            bool in = !((double)s > en || (double)s < st);
            if (in) ft += (float)((s <= 31) ? (s + 1) : (63 - s));
        }
        sft[tid] = ft;
    }
    __syncthreads();
    if (tid < 63) {                                   // W[s] = sum_g coef_g * member(s,g)
        float w = 0.0f;
        #pragma unroll
        for (int g = 0; g < 6; g++) {
            double st = q * (double)g;
            double en = q * (double)(g + 1);
            bool in = !((double)tid > en || (double)tid < st);
            if (in) w += ((float)(1 << g)) / sft[g];  // same float div + add order as before
        }
        gW[tid] = w;
    }
    if (tid == 63) gW[63] = 0.0f;
}

// ---------------- grade: one (b, hr, c, half) half-strip per block ----------------
// half 0: patches 0..15 (cols 0..271); half 1: patches 16..30 (cols 256..511).
// 256 threads, 43.9 KB static smem -> 5 CTAs/SM.
__global__ __launch_bounds__(256) void grade_kernel(const float* __restrict__ x) {
    __shared__ __align__(16) float strip[32 * STRIDE_S];
    __shared__ __align__(16) float U1[16 * 32];
    __shared__ __align__(16) float V1[16 * 32];
    __shared__ __align__(16) float U2[16 * 32];
    __shared__ __align__(16) float V2[16 * 32];
    __shared__ float Wt[64];
    __shared__ float gpart[8 * 16];

    const int idx0 = blockIdx.x;              // (((b*31 + hr)*3 + c)*2 + half)
    const int half = idx0 & 1;
    const int bhc  = idx0 >> 1;
    const int c    = bhc % 3;
    const int bh   = bhc / 3;
    const int hr   = bh % NH;
    const int b    = bh / NH;
    const int tid  = threadIdx.x;
    const int lane = tid & 31;
    const int wq   = tid >> 5;                // warp id 0..7

    const int colbase = half ? 256 : 0;
    const int ncols4  = half ? 64 : 68;       // float4 per row
    const int npat    = half ? 15 : 16;
    const int p0      = half ? 16 : 0;

    // D half-matrix column for this lane (shared by both stages)
    float dreg[16];
    #pragma unroll
    for (int jp = 0; jp < 16; jp++) dreg[jp] = __ldg(&gDT[jp * 32 + lane]);
    if (tid < 64) Wt[tid] = gW[tid];

    // load half-strip: rows 16hr..16hr+31, cols colbase..colbase+4*ncols4-1
    const float* xs = x + (((size_t)(b * NC + c)) * IH + hr * 16) * IW + colbase;
    const int nf4 = ncols4 * 32;
    for (int idx = tid; idx < nf4; idx += 256) {
        int r = idx / ncols4;
        int qq = idx - r * ncols4;
        float4 g4 = *(const float4*)(xs + (size_t)r * IW + qq * 4);
        float* row = strip + r * STRIDE_S + qq * 4;
        row[0] = g4.x; row[1] = g4.y; row[2] = g4.z; row[3] = g4.w;
    }
    __syncthreads();

    // rho row-permutation: stage-1 quad 4*w covers rows {2w, 2w+1, 30-2w, 31-2w}
    const int rho = (lane < 16) ? (2 * lane - (lane & 1))
                                : ((lane & 1) ? (65 - 2 * lane) : (62 - 2 * lane));

    for (int pp = 0; pp < npat; pp++) {
        const int off = pp * 16;              // local col base within strip

        // fold-1 (columns): r = lane, jp = wq (+8). conflict-free (stride 273).
        #pragma unroll
        for (int s = 0; s < 2; s++) {
            int jp = wq + 8 * s;
            const float* row = strip + lane * STRIDE_S + off;
            float a  = row[jp];
            float bb = row[31 - jp];
            U1[jp * 32 + rho] = a + bb;
            V1[jp * 32 + rho] = a - bb;
        }
        __syncthreads();

        // stage 1 + fused fold-2: lane = k, warp wq -> 4 symmetric rows
        {
            const float* Wb = (lane & 1) ? V1 : U1;
            float a0 = 0.f, a1 = 0.f, a2 = 0.f, a3 = 0.f;
            #pragma unroll
            for (int jp = 0; jp < 16; jp++) {
                float4 w = *(const float4*)(Wb + jp * 32 + 4 * wq);  // uniform per warp
                float d = dreg[jp];
                a0 = fmaf(w.x, d, a0);
                a1 = fmaf(w.y, d, a1);
                a2 = fmaf(w.z, d, a2);
                a3 = fmaf(w.w, d, a3);
            }
            U2[(2 * wq) * 32 + lane]     = a0 + a3;
            U2[(2 * wq + 1) * 32 + lane] = a1 + a2;
            V2[(2 * wq) * 32 + lane]     = a0 - a3;
            V2[(2 * wq + 1) * 32 + lane] = a1 - a2;
        }
        __syncthreads();

        // stage 2 + grade partial: lane = i, warp wq -> k quad
        {
            const float* Wb = (lane & 1) ? V2 : U2;
            float a0 = 0.f, a1 = 0.f, a2 = 0.f, a3 = 0.f;
            #pragma unroll
            for (int rp = 0; rp < 16; rp++) {
                float4 w = *(const float4*)(Wb + rp * 32 + 4 * wq);
                float d = dreg[rp];
                a0 = fmaf(w.x, d, a0);
                a1 = fmaf(w.y, d, a1);
                a2 = fmaf(w.z, d, a2);
                a3 = fmaf(w.w, d, a3);
            }
            const int k0 = 4 * wq;
            float g;
            g  = __logf(fabsf(a0) + 1.0f) * Wt[lane + k0 + 0];
            g += __logf(fabsf(a1) + 1.0f) * Wt[lane + k0 + 1];
            g += __logf(fabsf(a2) + 1.0f) * Wt[lane + k0 + 2];
            g += __logf(fabsf(a3) + 1.0f) * Wt[lane + k0 + 3];
            #pragma unroll
            for (int o = 16; o > 0; o >>= 1) g += __shfl_down_sync(0xFFFFFFFFu, g, o);
            if (lane == 0) gpart[wq * 16 + pp] = g;
        }
        __syncthreads();   // protects U/V reuse next patch; final iteration covers gpart
    }

    // deferred 8-warp sums -> gGradeC
    if (tid < npat) {
        float s = 0.f;
        #pragma unroll
        for (int w = 0; w < 8; w++) s += gpart[w * 16 + tid];
        int pl = b * NPATCH + hr * NH + (p0 + tid);
        gGradeC[pl * 4 + c] = s;
    }
}

// ---------------- selection: stable-argsort-compatible top2/bottom2 ----------------
__global__ void select_kernel() {
    __shared__ unsigned long long smin[256][2];
    __shared__ unsigned long long smax[256][2];
    const int b   = blockIdx.x;
    const int tid = threadIdx.x;
    const float* gr = &gGradeC[b * NPATCH * 4];

    unsigned long long mn1 = ~0ull, mn2 = ~0ull, mx1 = 0ull, mx2 = 0ull;
    for (int l = tid; l < NPATCH; l += 256) {
        float val = gr[l * 4 + 0] + gr[l * 4 + 1] + gr[l * 4 + 2];
        unsigned int ub = __float_as_uint(val);
        ub = (ub & 0x80000000u) ? ~ub : (ub | 0x80000000u);   // order-preserving map
        unsigned long long key = ((unsigned long long)ub << 32) | (unsigned)l;
        if (key < mn1) { mn2 = mn1; mn1 = key; } else if (key < mn2) { mn2 = key; }
        if (key > mx1) { mx2 = mx1; mx1 = key; } else if (key > mx2) { mx2 = key; }
    }
    smin[tid][0] = mn1; smin[tid][1] = mn2;
    smax[tid][0] = mx1; smax[tid][1] = mx2;
    __syncthreads();
    for (int s = 128; s > 0; s >>= 1) {
        if (tid < s) {
            unsigned long long a1 = smin[tid][0], a2 = smin[tid][1];
            unsigned long long b1 = smin[tid + s][0], b2 = smin[tid + s][1];
            smin[tid][0] = min(a1, b1);
            smin[tid][1] = min(max(a1, b1), min(a2, b2));
            a1 = smax[tid][0]; a2 = smax[tid][1];
            b1 = smax[tid + s][0]; b2 = smax[tid + s][1];
            smax[tid][0] = max(a1, b1);
            smax[tid][1] = max(min(a1, b1), max(a2, b2));
        }
        __syncthreads();
    }
    if (tid == 0) {
        gSel[b * 4 + 0] = (int)(smin[0][0] & 0xFFFFFFFFull);  // minmin  = idx[0]
        gSel[b * 4 + 1] = (int)(smax[0][0] & 0xFFFFFFFFull);  // maxmax  = idx[-1]
        gSel[b * 4 + 2] = (int)(smin[0][1] & 0xFFFFFFFFull);  // minmin1 = idx[1]
        gSel[b * 4 + 3] = (int)(smax[0][1] & 0xFFFFFFFFull);  // maxmax1 = idx[-2]
    }
}

// ---------------- gather: level_y == patch (orthogonal DCT round-trip) ----------------
__global__ void gather_kernel(const float* __restrict__ x, float* __restrict__ out) {
    const int id  = blockIdx.x;            // sel*48 + b*3 + c
    const int sel = id / 48;
    const int bc  = id - sel * 48;
    const int b   = bc / 3;
    const int c   = bc - b * 3;
    const int l   = gSel[b * 4 + sel];
    const int hr  = l / NH;
    const int wc  = l - hr * NH;

    const float4* src = (const float4*)(x + (((size_t)(b * NC + c)) * IH + hr * 16) * IW + wc * 16);
    float4* dst = (float4*)(out + (size_t)id * 1024);
    const int t  = threadIdx.x;            // 256 threads, one float4 each
    const int r  = t >> 3;
    const int jq = t & 7;
    dst[r * 8 + jq] = src[r * (IW / 4) + jq];
}

// ---------------- launch ----------------
extern "C" void kernel_launch(void* const* d_in, const int* in_sizes, int n_in,
                              void* d_out, int out_size) {
    const float* x = (const float*)d_in[0];
    float* out = (float*)d_out;
    init_kernel<<<1, 512>>>();
    grade_kernel<<<NB * NH * NC * 2, 256>>>(x);
    select_kernel<<<NB, 256>>>();
    gather_kernel<<<4 * NB * NC, 256>>>(x, out);
}

// round 9
// speedup vs baseline: 2.0807x; 1.4628x over previous
#include <cuda_runtime.h>
#include <math.h>
#include <stdint.h>

#define WSZ    32
#define NH     31
#define NPATCH (NH * NH)   // 961
#define NB     16
#define NC     3
#define IH     512
#define IW     512

#define STRIDE_S 273                    // strip row stride in floats (odd -> conflict-free)
#define SMEM_FLOATS (32 * STRIDE_S + 8 * 512 + 64 + 128)
#define SMEM_BYTES  (SMEM_FLOATS * 4)   // 52,096 B

// ---------------- device globals (no allocations allowed) ----------------
__device__ float gDT[16 * 32];            // gDT[j*32+i] = D[i][j], j < 16 (symmetry half)
__device__ float gW[64];                  // diagonal weight table W[s], s = i+k in [0,62]
__device__ float gGradeC[NB * NPATCH * 4]; // per-channel partial grades, stride 4 (c=0..2)
__device__ int   gSel[NB * 4];            // per batch: [minmin, maxmax, minmin1, maxmax1]

// ---------------- packed f32x2 helpers (sm_103a) ----------------
__device__ __forceinline__ uint64_t pack2(float v) {
    uint64_t r; asm("mov.b64 %0, {%1, %1};" : "=l"(r) : "f"(v)); return r;
}
__device__ __forceinline__ void unpack2(float& lo, float& hi, uint64_t v) {
    asm("mov.b64 {%0, %1}, %2;" : "=f"(lo), "=f"(hi) : "l"(v));
}
__device__ __forceinline__ void fma2(uint64_t& a, uint64_t x, uint64_t y) {
    asm("fma.rn.f32x2 %0, %1, %2, %0;" : "+l"(a) : "l"(x), "l"(y));
}
__device__ __forceinline__ void lds_v2u64(uint64_t& w0, uint64_t& w1, uint32_t addr) {
    asm("ld.shared.v2.u64 {%0, %1}, [%2];" : "=l"(w0), "=l"(w1) : "r"(addr));
}
__device__ __forceinline__ void barsync128(int id) {
    asm volatile("bar.sync %0, 128;" :: "r"(id) : "memory");
}

// ---------------- init: DCT matrix + grade-weight table (fully parallel) ----------------
__global__ void init_kernel() {
    __shared__ float sft[6];
    const int tid = threadIdx.x;         // 512 threads
    const int i = tid >> 4, j = tid & 15;
    double scale = (i == 0) ? sqrt(1.0 / 32.0) : sqrt(2.0 / 32.0);
    double v = scale * cos((((double)j + 0.5) * 3.141592653589793) * (double)i / 32.0);
    gDT[j * 32 + i] = (float)v;

    const double q = (double)WSZ * 2.0 / 6.0;         // 64/6 in IEEE double, like numpy
    if (tid < 6) {
        double st = q * (double)tid;
        double en = q * (double)(tid + 1);
        float ft = 0.0f;
        for (int s = 0; s <= 62; s++) {
            bool in = !((double)s > en || (double)s < st);
            if (in) ft += (float)((s <= 31) ? (s + 1) : (63 - s));
        }
        sft[tid] = ft;
    }
    __syncthreads();
    if (tid < 63) {
        float w = 0.0f;
        #pragma unroll
        for (int g = 0; g < 6; g++) {
            double st = q * (double)g;
            double en = q * (double)(g + 1);
            bool in = !((double)tid > en || (double)tid < st);
            if (in) w += ((float)(1 << g)) / sft[g];
        }
        gW[tid] = w;
    }
    if (tid == 63) gW[63] = 0.0f;
}

// ---------------- grade: (b, hr, c, half-strip) per block; 2 patches in flight ----------------
// 256 threads = two decoupled 128-thread groups (named barriers), one patch each.
// Per thread: ks {k1, k1+16}; packed f32x2 accumulators over row/k pairs.
__global__ __launch_bounds__(256) void grade_kernel(const float* __restrict__ x) {
    extern __shared__ __align__(16) float sm[];
    float* strip = sm;                        // [32][273]
    float* U1b   = sm + 32 * STRIDE_S;        // [2][16][32]
    float* V1b   = U1b + 1024;
    float* U2b   = V1b + 1024;
    float* V2b   = U2b + 1024;
    float* Wt    = V2b + 1024;                // [64]
    float* gpart = Wt + 64;                   // [8][16]

    const int idx0 = blockIdx.x;              // (((b*31 + hr)*3 + c)*2 + hs)
    const int hs   = idx0 & 1;
    const int bhc  = idx0 >> 1;
    const int c    = bhc % 3;
    const int bh   = bhc / 3;
    const int hr   = bh % NH;
    const int b    = bh / NH;
    const int tid  = threadIdx.x;
    const int lane = tid & 31;
    const int sub  = tid >> 7;                // 128-thread group id
    const int st   = tid & 127;
    const int sw   = st >> 5;                 // warp-in-group 0..3
    const int k1   = st & 15;                 // this thread's ks: k1, k1+16
    const int q    = st >> 4;                 // row/k quad 0..7

    const int colbase = hs ? 256 : 0;
    const int ncols4  = hs ? 64 : 68;
    const int npat    = hs ? 15 : 16;

    // D half-matrix columns for k1 and k1+16 (reused by stage 2: i1 = k1)
    float dregA[16], dregB[16];
    #pragma unroll
    for (int jp = 0; jp < 16; jp++) {
        dregA[jp] = __ldg(&gDT[jp * 32 + k1]);
        dregB[jp] = __ldg(&gDT[jp * 32 + k1 + 16]);
    }
    if (tid < 64) Wt[tid] = gW[tid];

    // load half-strip (both groups cooperate)
    const float* xs = x + (((size_t)(b * NC + c)) * IH + hr * 16) * IW + colbase;
    const int nf4 = ncols4 * 32;
    for (int idx = tid; idx < nf4; idx += 256) {
        int r  = idx / ncols4;
        int qq = idx - r * ncols4;
        float4 g4 = *(const float4*)(xs + (size_t)r * IW + qq * 4);
        float* row = strip + r * STRIDE_S + qq * 4;
        row[0] = g4.x; row[1] = g4.y; row[2] = g4.z; row[3] = g4.w;
    }
    __syncthreads();

    float* U1s = U1b + sub * 512;
    float* V1s = V1b + sub * 512;
    float* U2s = U2b + sub * 512;
    float* V2s = V2b + sub * 512;
    const uint32_t u1a = (uint32_t)__cvta_generic_to_shared(U1s);
    const uint32_t v1a = (uint32_t)__cvta_generic_to_shared(V1s);
    const uint32_t u2a = (uint32_t)__cvta_generic_to_shared(U2s);
    const uint32_t v2a = (uint32_t)__cvta_generic_to_shared(V2s);
    const uint32_t wb1 = (k1 & 1) ? v1a : u1a;    // parity(k1) == parity(k1+16)
    const uint32_t wb2 = (k1 & 1) ? v2a : u2a;

    // rho': pos 4q+{0,1,2,3} = rows {2q, 2q+1, 31-2q, 30-2q}
    const int rho = (lane < 16) ? (2 * lane - (lane & 1))
                                : ((lane & 1) ? (64 - 2 * lane) : (63 - 2 * lane));
    const int bid = 1 + sub;                  // named barrier id per group

    // fold-1 for local patch pp: columns folded, rows rho-permuted
    #define FOLD(pp) do {                                                   \
        const float* rowp = strip + lane * STRIDE_S + (pp) * 16;            \
        _Pragma("unroll")                                                   \
        for (int s = 0; s < 4; s++) {                                       \
            int jp = sw + 4 * s;                                            \
            float a  = rowp[jp];                                            \
            float bb = rowp[31 - jp];                                       \
            U1s[jp * 32 + rho] = a + bb;                                    \
            V1s[jp * 32 + rho] = a - bb;                                    \
        }                                                                   \
    } while (0)

    if (sub < npat) FOLD(sub);                // pp = 2*0 + sub
    barsync128(bid);

    for (int it = 0; it < 8; it++) {
        const int pp = 2 * it + sub;
        const bool valid = pp < npat;

        // ---- stage 1 + fused fold-2 ----
        if (valid) {
            uint64_t A01a = 0, A32a = 0, A01b = 0, A32b = 0;
            #pragma unroll
            for (int jp = 0; jp < 16; jp++) {
                uint64_t w01, w32;
                lds_v2u64(w01, w32, wb1 + (uint32_t)(jp * 32 + 4 * q) * 4u);
                uint64_t dd1 = pack2(dregA[jp]);
                uint64_t dd2 = pack2(dregB[jp]);
                fma2(A01a, w01, dd1); fma2(A32a, w32, dd1);
                fma2(A01b, w01, dd2); fma2(A32b, w32, dd2);
            }
            float o0, o1, o31, o30;
            unpack2(o0, o1, A01a); unpack2(o31, o30, A32a);
            U2s[(2 * q) * 32 + k1]          = o0 + o31;
            V2s[(2 * q) * 32 + k1]          = o0 - o31;
            U2s[(2 * q + 1) * 32 + k1]      = o1 + o30;
            V2s[(2 * q + 1) * 32 + k1]      = o1 - o30;
            unpack2(o0, o1, A01b); unpack2(o31, o30, A32b);
            U2s[(2 * q) * 32 + k1 + 16]     = o0 + o31;
            V2s[(2 * q) * 32 + k1 + 16]     = o0 - o31;
            U2s[(2 * q + 1) * 32 + k1 + 16] = o1 + o30;
            V2s[(2 * q + 1) * 32 + k1 + 16] = o1 - o30;
        }
        barsync128(bid);

        // ---- stage 2 + grade, overlapped with fold of next patch ----
        if (valid) {
            uint64_t P0a = 0, P1a = 0, P0b = 0, P1b = 0;
            #pragma unroll
            for (int rp = 0; rp < 16; rp++) {
                uint64_t w01, w23;
                lds_v2u64(w01, w23, wb2 + (uint32_t)(rp * 32 + 4 * q) * 4u);
                uint64_t dd1 = pack2(dregA[rp]);
                uint64_t dd2 = pack2(dregB[rp]);
                fma2(P0a, w01, dd1); fma2(P1a, w23, dd1);
                fma2(P0b, w01, dd2); fma2(P1b, w23, dd2);
            }
            float x0, x1, x2, x3, y0, y1, y2, y3;
            unpack2(x0, x1, P0a); unpack2(x2, x3, P1a);
            unpack2(y0, y1, P0b); unpack2(y2, y3, P1b);
            const int k0 = 4 * q;
            float g;
            g  = __logf(fabsf(x0) + 1.0f) * Wt[k1 + k0 + 0];
            g += __logf(fabsf(x1) + 1.0f) * Wt[k1 + k0 + 1];
            g += __logf(fabsf(x2) + 1.0f) * Wt[k1 + k0 + 2];
            g += __logf(fabsf(x3) + 1.0f) * Wt[k1 + k0 + 3];
            g += __logf(fabsf(y0) + 1.0f) * Wt[k1 + 16 + k0 + 0];
            g += __logf(fabsf(y1) + 1.0f) * Wt[k1 + 16 + k0 + 1];
            g += __logf(fabsf(y2) + 1.0f) * Wt[k1 + 16 + k0 + 2];
            g += __logf(fabsf(y3) + 1.0f) * Wt[k1 + 16 + k0 + 3];
            #pragma unroll
            for (int o = 16; o > 0; o >>= 1) g += __shfl_down_sync(0xFFFFFFFFu, g, o);
            if (lane == 0) gpart[(sub * 4 + sw) * 16 + it] = g;
        }
        const int ppn = 2 * (it + 1) + sub;
        if (it < 7 && ppn < npat) FOLD(ppn);
        barsync128(bid);
    }
    #undef FOLD

    __syncthreads();
    // deferred 4-warp sums -> gGradeC (patch pp: sub = pp&1, it = pp>>1)
    if (tid < npat) {
        const int su = tid & 1, itp = tid >> 1;
        float s = 0.f;
        #pragma unroll
        for (int w = 0; w < 4; w++) s += gpart[(su * 4 + w) * 16 + itp];
        int pl = b * NPATCH + hr * NH + (hs ? 16 : 0) + tid;
        gGradeC[pl * 4 + c] = s;
    }
}

// ---------------- selection: stable-argsort-compatible top2/bottom2 ----------------
__global__ void select_kernel() {
    __shared__ unsigned long long smin[256][2];
    __shared__ unsigned long long smax[256][2];
    const int b   = blockIdx.x;
    const int tid = threadIdx.x;
    const float* gr = &gGradeC[b * NPATCH * 4];

    unsigned long long mn1 = ~0ull, mn2 = ~0ull, mx1 = 0ull, mx2 = 0ull;
    for (int l = tid; l < NPATCH; l += 256) {
        float val = gr[l * 4 + 0] + gr[l * 4 + 1] + gr[l * 4 + 2];
        unsigned int ub = __float_as_uint(val);
        ub = (ub & 0x80000000u) ? ~ub : (ub | 0x80000000u);   // order-preserving map
        unsigned long long key = ((unsigned long long)ub << 32) | (unsigned)l;
        if (key < mn1) { mn2 = mn1; mn1 = key; } else if (key < mn2) { mn2 = key; }
        if (key > mx1) { mx2 = mx1; mx1 = key; } else if (key > mx2) { mx2 = key; }
    }
    smin[tid][0] = mn1; smin[tid][1] = mn2;
    smax[tid][0] = mx1; smax[tid][1] = mx2;
    __syncthreads();
    for (int s = 128; s > 0; s >>= 1) {
        if (tid < s) {
            unsigned long long a1 = smin[tid][0], a2 = smin[tid][1];
            unsigned long long b1 = smin[tid + s][0], b2 = smin[tid + s][1];
            smin[tid][0] = min(a1, b1);
            smin[tid][1] = min(max(a1, b1), min(a2, b2));
            a1 = smax[tid][0]; a2 = smax[tid][1];
            b1 = smax[tid + s][0]; b2 = smax[tid + s][1];
            smax[tid][0] = max(a1, b1);
            smax[tid][1] = max(min(a1, b1), max(a2, b2));
        }
        __syncthreads();
    }
    if (tid == 0) {
        gSel[b * 4 + 0] = (int)(smin[0][0] & 0xFFFFFFFFull);  // minmin  = idx[0]
        gSel[b * 4 + 1] = (int)(smax[0][0] & 0xFFFFFFFFull);  // maxmax  = idx[-1]
        gSel[b * 4 + 2] = (int)(smin[0][1] & 0xFFFFFFFFull);  // minmin1 = idx[1]
        gSel[b * 4 + 3] = (int)(smax[0][1] & 0xFFFFFFFFull);  // maxmax1 = idx[-2]
    }
}

// ---------------- gather: level_y == patch (orthogonal DCT round-trip) ----------------
__global__ void gather_kernel(const float* __restrict__ x, float* __restrict__ out) {
    const int id  = blockIdx.x;            // sel*48 + b*3 + c
    const int sel = id / 48;
    const int bc  = id - sel * 48;
    const int b   = bc / 3;
    const int c   = bc - b * 3;
    const int l   = gSel[b * 4 + sel];
    const int hr  = l / NH;
    const int wc  = l - hr * NH;

    const float4* src = (const float4*)(x + (((size_t)(b * NC + c)) * IH + hr * 16) * IW + wc * 16);
    float4* dst = (float4*)(out + (size_t)id * 1024);
    const int t  = threadIdx.x;            // 256 threads, one float4 each
    const int r  = t >> 3;
    const int jq = t & 7;
    dst[r * 8 + jq] = src[r * (IW / 4) + jq];
}

// ---------------- launch ----------------
extern "C" void kernel_launch(void* const* d_in, const int* in_sizes, int n_in,
                              void* d_out, int out_size) {
    const float* x = (const float*)d_in[0];
    float* out = (float*)d_out;
    cudaFuncSetAttribute(grade_kernel, cudaFuncAttributeMaxDynamicSharedMemorySize, SMEM_BYTES);
    init_kernel<<<1, 512>>>();
    grade_kernel<<<NB * NH * NC * 2, 256, SMEM_BYTES>>>(x);
    select_kernel<<<NB, 256>>>();
    gather_kernel<<<4 * NB * NC, 256>>>(x, out);
}